// round 2
// baseline (speedup 1.0000x reference)
#include <cuda_runtime.h>
#include <cuda_bf16.h>
#include <stdint.h>
#include <math.h>

#define NB   64
#define NQ   900
#define NT   128
#define NCLS 91

typedef unsigned long long u64;
typedef unsigned int       u32;

// Presorted per-row cost keys: ((ordered_float)<<32 | col), ascending.
// +8 pad so the 4-wide prefetch in the greedy walk never faults.
__device__ u64 g_sorted[(size_t)NB * NQ * NT + 8];

// monotonic float -> uint mapping (ascending)
__device__ __forceinline__ u32 f2ord(float f) {
    u32 u = __float_as_uint(f);
    return (u & 0x80000000u) ? ~u : (u | 0x80000000u);
}

// ---------------------------------------------------------------------------
// Kernel 1: fused cost + per-row bitonic sort.
// Block: 256 threads (8 warps); each warp handles 2 rows; grid (57, 64).
// Row layout for sort: element idx = lane*4 + r  (r = 0..3 registers).
// ---------------------------------------------------------------------------
__global__ void __launch_bounds__(256) cost_sort_kernel(
    const float* __restrict__ logits,   // [B,Q,91]
    const float* __restrict__ pboxes,   // [B,Q,4]
    const int*   __restrict__ labels,   // [B,T]
    const float* __restrict__ tboxes,   // [B,T,4]
    float* __restrict__ Cout)           // [B,Q,T]
{
    const int b    = blockIdx.y;
    const int tid  = threadIdx.x;
    const int lane = tid & 31;
    const int wid  = tid >> 5;

    __shared__ float4 s_tb[NT];   // target cxcywh
    __shared__ float4 s_tx[NT];   // target xyxy
    __shared__ float  s_ta[NT];   // target area
    __shared__ int    s_lab[NT];
    __shared__ float  s_exp[8][92];

    if (tid < NT) {
        const float* tb = tboxes + ((size_t)b * NT + tid) * 4;
        float cx = tb[0], cy = tb[1], w = tb[2], h = tb[3];
        s_tb[tid] = make_float4(cx, cy, w, h);
        float x0 = cx - 0.5f * w, y0 = cy - 0.5f * h;
        float x1 = cx + 0.5f * w, y1 = cy + 0.5f * h;
        s_tx[tid] = make_float4(x0, y0, x1, y1);
        s_ta[tid] = (x1 - x0) * (y1 - y0);
        s_lab[tid] = labels[b * NT + tid];
    }
    __syncthreads();

    for (int rr = 0; rr < 2; rr++) {
        int q = blockIdx.x * 16 + rr * 8 + wid;   // warp-uniform
        if (q >= NQ) continue;

        // ---- softmax over 91 logits (warp-level) ----
        const float* lr = logits + ((size_t)b * NQ + q) * NCLS;
        float l0 = lr[lane];
        float l1 = lr[lane + 32];                         // 32..63 < 91
        float l2 = (lane + 64 < NCLS) ? lr[lane + 64] : -INFINITY;
        float m = fmaxf(fmaxf(l0, l1), l2);
        #pragma unroll
        for (int o = 16; o; o >>= 1) m = fmaxf(m, __shfl_xor_sync(0xffffffffu, m, o));
        float e0 = expf(l0 - m), e1 = expf(l1 - m);
        float e2 = (lane + 64 < NCLS) ? expf(l2 - m) : 0.0f;
        float ssum = e0 + e1 + e2;
        #pragma unroll
        for (int o = 16; o; o >>= 1) ssum += __shfl_xor_sync(0xffffffffu, ssum, o);
        s_exp[wid][lane] = e0;
        s_exp[wid][lane + 32] = e1;
        if (lane + 64 < NCLS) s_exp[wid][lane + 64] = e2;
        __syncwarp();
        float inv = 1.0f / ssum;

        // ---- prediction box ----
        const float* pbp = pboxes + ((size_t)b * NQ + q) * 4;
        float pcx = pbp[0], pcy = pbp[1], pw = pbp[2], ph = pbp[3];
        float px0 = pcx - 0.5f * pw, py0 = pcy - 0.5f * ph;
        float px1 = pcx + 0.5f * pw, py1 = pcy + 0.5f * ph;
        float pa  = (px1 - px0) * (py1 - py0);

        // ---- 4 costs per lane ----
        u64   key[4];
        float cst[4];
        #pragma unroll
        for (int r = 0; r < 4; r++) {
            int t = (lane << 2) | r;
            float4 tb = s_tb[t];
            float4 tx = s_tx[t];
            float pl  = s_exp[wid][s_lab[t]] * inv;
            float l1c = fabsf(pcx - tb.x) + fabsf(pcy - tb.y)
                      + fabsf(pw - tb.z) + fabsf(ph - tb.w);
            float ix0 = fmaxf(px0, tx.x), iy0 = fmaxf(py0, tx.y);
            float ix1 = fminf(px1, tx.z), iy1 = fminf(py1, tx.w);
            float inter = fmaxf(ix1 - ix0, 0.0f) * fmaxf(iy1 - iy0, 0.0f);
            float uni   = pa + s_ta[t] - inter;
            float iou   = inter / uni;
            float cx0 = fminf(px0, tx.x), cy0 = fminf(py0, tx.y);
            float cx1 = fmaxf(px1, tx.z), cy1 = fmaxf(py1, tx.w);
            float ac  = fmaxf(cx1 - cx0, 0.0f) * fmaxf(cy1 - cy0, 0.0f);
            float giou = iou - (ac - uni) / ac;
            float c = -pl + 5.0f * l1c - 2.0f * giou;
            cst[r] = c;
            key[r] = ((u64)f2ord(c) << 32) | (u32)t;
        }

        // write cost matrix row (coalesced float4)
        float* crow = Cout + ((size_t)b * NQ + q) * NT;
        *(float4*)(crow + (lane << 2)) = make_float4(cst[0], cst[1], cst[2], cst[3]);

        // ---- warp bitonic sort of 128 u64 keys, 4 per lane ----
        #pragma unroll
        for (int k = 2; k <= 128; k <<= 1) {
            #pragma unroll
            for (int j = k >> 1; j > 0; j >>= 1) {
                if (j >= 4) {
                    int lm = j >> 2;
                    #pragma unroll
                    for (int r = 0; r < 4; r++) {
                        u64 o = __shfl_xor_sync(0xffffffffu, key[r], lm);
                        int idx = (lane << 2) | r;
                        bool up  = ((idx & k) == 0);
                        bool low = ((idx & j) == 0);
                        u64 mn = key[r] < o ? key[r] : o;
                        u64 mx = key[r] < o ? o : key[r];
                        key[r] = (up == low) ? mn : mx;
                    }
                } else if (j == 2) {
                    bool up = (((lane << 2) & k) == 0);   // k>=4: same for all r
                    { u64 a = key[0], c = key[2];
                      bool sw = up ? (a > c) : (a < c);
                      if (sw) { key[0] = c; key[2] = a; } }
                    { u64 a = key[1], c = key[3];
                      bool sw = up ? (a > c) : (a < c);
                      if (sw) { key[1] = c; key[3] = a; } }
                } else {  // j == 1
                    { int idx = (lane << 2);
                      bool up = ((idx & k) == 0);
                      u64 a = key[0], c = key[1];
                      bool sw = up ? (a > c) : (a < c);
                      if (sw) { key[0] = c; key[1] = a; } }
                    { int idx = (lane << 2) | 2;
                      bool up = ((idx & k) == 0);
                      u64 a = key[2], c = key[3];
                      bool sw = up ? (a > c) : (a < c);
                      if (sw) { key[2] = c; key[3] = a; } }
                }
            }
        }

        u64* srow = g_sorted + ((size_t)b * NQ + q) * NT;
        ((ulonglong2*)(srow + (lane << 2)))[0] = make_ulonglong2(key[0], key[1]);
        ((ulonglong2*)(srow + (lane << 2)))[1] = make_ulonglong2(key[2], key[3]);
    }
}

// ---------------------------------------------------------------------------
// Kernel 2: greedy matching over presorted rows.  One block per batch.
// ---------------------------------------------------------------------------
__global__ void __launch_bounds__(256) greedy_kernel(float* __restrict__ out)
{
    const int b    = blockIdx.x;
    const int tid  = threadIdx.x;
    const int lane = tid & 31;
    const int wid  = tid >> 5;
    const u64* __restrict__ sb = g_sorted + (size_t)b * NQ * NT;

    __shared__ u32            rmin[NQ];      // ordered-uint current row min
    __shared__ unsigned char  rcol[NQ];      // current argmin col (0xFF = matched)
    __shared__ unsigned short rptr[NQ];      // next unread sorted-list index
    __shared__ u64            s_wred[8];
    __shared__ u32            colrem[4];     // removed-column bitmap
    __shared__ int            s_j;
    __shared__ int            s_src[NT], s_tgt[NT];

    for (int q = tid; q < NQ; q += 256) {
        u64 k = sb[(size_t)q * NT];
        rmin[q] = (u32)(k >> 32);
        rcol[q] = (unsigned char)(k & 0xFFu);
        rptr[q] = 1;
    }
    if (tid < 4) colrem[tid] = 0u;
    __syncthreads();

    for (int t = 0; t < NT; t++) {
        // ---- global argmin: key = (rmin, row) — exact flattened-argmin order ----
        u64 best = ~0ull;
        for (int q = tid; q < NQ; q += 256) {
            u64 kk = ((u64)rmin[q] << 32) | (u32)q;
            best = kk < best ? kk : best;
        }
        #pragma unroll
        for (int o = 16; o; o >>= 1) {
            u64 ob = __shfl_down_sync(0xffffffffu, best, o);
            best = ob < best ? ob : best;
        }
        if (lane == 0) s_wred[wid] = best;
        __syncthreads();
        if (tid == 0) {
            u64 bb = s_wred[0];
            #pragma unroll
            for (int w = 1; w < 8; w++) { u64 o = s_wred[w]; bb = o < bb ? o : bb; }
            int i = (int)(u32)bb;
            int j = (int)rcol[i];
            s_j = j;
            s_src[t] = i;
            s_tgt[t] = j;
            rmin[i] = 0xFFFFFFFFu;
            rcol[i] = 0xFF;
            colrem[j >> 5] |= (1u << (j & 31));
        }
        __syncthreads();
        if (t == NT - 1) break;

        // ---- advance rows whose current col was just removed ----
        const int j = s_j;
        for (int w = tid; w < NQ / 4; w += 256) {
            u32 word = ((const u32*)rcol)[w];
            #pragma unroll
            for (int bpos = 0; bpos < 4; bpos++) {
                if (((word >> (bpos * 8)) & 0xFFu) == (u32)j) {
                    int q = w * 4 + bpos;
                    const u64* lst = sb + (size_t)q * NT;
                    int p = rptr[q];
                    u32 nv, nc;
                    for (;;) {
                        u64 k0 = lst[p];
                        u64 k1 = lst[p + 1];
                        u64 k2 = lst[p + 2];
                        u64 k3 = lst[p + 3];
                        u32 c0 = (u32)k0 & 0xFFu;
                        if (!((colrem[c0 >> 5] >> (c0 & 31)) & 1u)) { nv = (u32)(k0 >> 32); nc = c0; p += 1; break; }
                        u32 c1 = (u32)k1 & 0xFFu;
                        if (!((colrem[c1 >> 5] >> (c1 & 31)) & 1u)) { nv = (u32)(k1 >> 32); nc = c1; p += 2; break; }
                        u32 c2 = (u32)k2 & 0xFFu;
                        if (!((colrem[c2 >> 5] >> (c2 & 31)) & 1u)) { nv = (u32)(k2 >> 32); nc = c2; p += 3; break; }
                        u32 c3 = (u32)k3 & 0xFFu;
                        if (!((colrem[c3 >> 5] >> (c3 & 31)) & 1u)) { nv = (u32)(k3 >> 32); nc = c3; p += 4; break; }
                        p += 4;
                    }
                    rmin[q] = nv;
                    rcol[q] = (unsigned char)nc;
                    rptr[q] = (unsigned short)p;
                }
            }
        }
        __syncthreads();
    }

    __syncthreads();
    if (tid < NT) {
        out[b * NT + tid]           = (float)s_src[tid];
        out[NB * NT + b * NT + tid] = (float)s_tgt[tid];
    }
}

// ---------------------------------------------------------------------------
extern "C" void kernel_launch(void* const* d_in, const int* in_sizes, int n_in,
                              void* d_out, int out_size) {
    const float* logits = (const float*)d_in[0];   // [64,900,91]
    const float* pboxes = (const float*)d_in[1];   // [64,900,4]
    const int*   labels = (const int*)d_in[2];     // [64,128]
    const float* tboxes = (const float*)d_in[3];   // [64,128,4]
    float* out = (float*)d_out;

    float* Cout = out + 2 * NB * NT;   // C follows the two index blocks

    dim3 grid1((NQ + 15) / 16, NB);    // 57 x 64, 2 rows/warp
    cost_sort_kernel<<<grid1, 256>>>(logits, pboxes, labels, tboxes, Cout);

    greedy_kernel<<<NB, 256>>>(out);
}

// round 3
// speedup vs baseline: 2.8879x; 2.8879x over previous
#include <cuda_runtime.h>
#include <cuda_bf16.h>
#include <stdint.h>
#include <math.h>

#define NB   64
#define NQ   900
#define NT   128
#define NCLS 91

typedef unsigned long long u64;
typedef unsigned int       u32;

// monotonic float -> uint mapping (ascending)
__device__ __forceinline__ u32 f2ord(float f) {
    u32 u = __float_as_uint(f);
    return (u & 0x80000000u) ? ~u : (u | 0x80000000u);
}

// ---------------------------------------------------------------------------
// Kernel 1: cost matrix.  256 threads = 8 warps; each warp computes 2 rows
// (warp-level softmax, no block barriers in the row loop).  grid (57, 64).
// ---------------------------------------------------------------------------
__global__ void __launch_bounds__(256) cost_kernel(
    const float* __restrict__ logits,   // [B,Q,91]
    const float* __restrict__ pboxes,   // [B,Q,4]
    const int*   __restrict__ labels,   // [B,T]
    const float* __restrict__ tboxes,   // [B,T,4]
    float* __restrict__ Cout)           // [B,Q,T]
{
    const int b    = blockIdx.y;
    const int tid  = threadIdx.x;
    const int lane = tid & 31;
    const int wid  = tid >> 5;

    __shared__ float4 s_tb[NT];   // target cxcywh
    __shared__ float4 s_tx[NT];   // target xyxy
    __shared__ float  s_ta[NT];   // target area
    __shared__ int    s_lab[NT];
    __shared__ float  s_exp[8][92];

    if (tid < NT) {
        const float* tb = tboxes + ((size_t)b * NT + tid) * 4;
        float cx = tb[0], cy = tb[1], w = tb[2], h = tb[3];
        s_tb[tid] = make_float4(cx, cy, w, h);
        float x0 = cx - 0.5f * w, y0 = cy - 0.5f * h;
        float x1 = cx + 0.5f * w, y1 = cy + 0.5f * h;
        s_tx[tid] = make_float4(x0, y0, x1, y1);
        s_ta[tid] = (x1 - x0) * (y1 - y0);
        s_lab[tid] = labels[b * NT + tid];
    }
    __syncthreads();

    #pragma unroll
    for (int rr = 0; rr < 2; rr++) {
        int q = blockIdx.x * 16 + rr * 8 + wid;   // warp-uniform
        if (q >= NQ) continue;

        // ---- softmax over 91 logits (warp-level) ----
        const float* lr = logits + ((size_t)b * NQ + q) * NCLS;
        float l0 = lr[lane];
        float l1 = lr[lane + 32];
        float l2 = (lane + 64 < NCLS) ? lr[lane + 64] : -INFINITY;
        float m = fmaxf(fmaxf(l0, l1), l2);
        #pragma unroll
        for (int o = 16; o; o >>= 1) m = fmaxf(m, __shfl_xor_sync(0xffffffffu, m, o));
        float e0 = expf(l0 - m), e1 = expf(l1 - m);
        float e2 = (lane + 64 < NCLS) ? expf(l2 - m) : 0.0f;
        float ssum = e0 + e1 + e2;
        #pragma unroll
        for (int o = 16; o; o >>= 1) ssum += __shfl_xor_sync(0xffffffffu, ssum, o);
        s_exp[wid][lane] = e0;
        s_exp[wid][lane + 32] = e1;
        if (lane + 64 < NCLS) s_exp[wid][lane + 64] = e2;
        __syncwarp();
        float inv = 1.0f / ssum;

        // ---- prediction box ----
        const float* pbp = pboxes + ((size_t)b * NQ + q) * 4;
        float pcx = pbp[0], pcy = pbp[1], pw = pbp[2], ph = pbp[3];
        float px0 = pcx - 0.5f * pw, py0 = pcy - 0.5f * ph;
        float px1 = pcx + 0.5f * pw, py1 = pcy + 0.5f * ph;
        float pa  = (px1 - px0) * (py1 - py0);

        float cst[4];
        #pragma unroll
        for (int r = 0; r < 4; r++) {
            int t = (lane << 2) | r;
            float4 tb = s_tb[t];
            float4 tx = s_tx[t];
            float pl  = s_exp[wid][s_lab[t]] * inv;
            float l1c = fabsf(pcx - tb.x) + fabsf(pcy - tb.y)
                      + fabsf(pw - tb.z) + fabsf(ph - tb.w);
            float ix0 = fmaxf(px0, tx.x), iy0 = fmaxf(py0, tx.y);
            float ix1 = fminf(px1, tx.z), iy1 = fminf(py1, tx.w);
            float inter = fmaxf(ix1 - ix0, 0.0f) * fmaxf(iy1 - iy0, 0.0f);
            float uni   = pa + s_ta[t] - inter;
            float iou   = inter / uni;
            float cx0 = fminf(px0, tx.x), cy0 = fminf(py0, tx.y);
            float cx1 = fmaxf(px1, tx.z), cy1 = fmaxf(py1, tx.w);
            float ac  = fmaxf(cx1 - cx0, 0.0f) * fmaxf(cy1 - cy0, 0.0f);
            float giou = iou - (ac - uni) / ac;
            cst[r] = -pl + 5.0f * l1c - 2.0f * giou;
        }

        float* crow = Cout + ((size_t)b * NQ + q) * NT;
        *(float4*)(crow + (lane << 2)) = make_float4(cst[0], cst[1], cst[2], cst[3]);
    }
}

// ---------------------------------------------------------------------------
// Kernel 2: greedy matching with per-COLUMN cached minima (128 entries).
// key = (f2ord(cost) << 18) | (row << 8) | col  — lexicographic (v, i, j)
// equals the flattened row-major argmin order.  One block per batch.
// ---------------------------------------------------------------------------
__global__ void __launch_bounds__(256) greedy_kernel(
    const float* __restrict__ Cmat,    // [B,Q,T]
    float* __restrict__ out)           // [B*T src | B*T tgt | C]
{
    const int b    = blockIdx.x;
    const int tid  = threadIdx.x;
    const int lane = tid & 31;
    const int wid  = tid >> 5;
    const float* __restrict__ Cb = Cmat + (size_t)b * NQ * NT;

    __shared__ u64 colkey[NT];        // per-column min key (live rows only)
    __shared__ u32 rowdead[32];       // 900-bit bitmap
    __shared__ u64 wpart[4];
    __shared__ int list_[NT];
    __shared__ int s_cnt, s_i;
    __shared__ int s_src[NT], s_tgt[NT];

    if (tid < 32) rowdead[tid] = 0u;
    if (tid < NT) colkey[tid] = ~0ull;
    __syncthreads();

    // ---- init: 2 threads per column, coalesced row-major reads ----
    {
        const int j  = tid & 127;
        u64 best = ~0ull;
        for (int q = (tid >> 7); q < NQ; q += 2) {
            float v = Cb[q * NT + j];
            u64 k = ((u64)f2ord(v) << 18) | ((u32)q << 8) | (u32)j;
            best = k < best ? k : best;
        }
        atomicMin(&colkey[j], best);
    }
    __syncthreads();

    for (int t = 0; t < NT; t++) {
        // ---- argmin over 128 column keys ----
        u64 k = (tid < NT) ? colkey[tid] : ~0ull;
        #pragma unroll
        for (int o = 16; o; o >>= 1) {
            u64 ok = __shfl_down_sync(0xffffffffu, k, o);
            k = ok < k ? ok : k;
        }
        if (lane == 0 && wid < 4) wpart[wid] = k;
        __syncthreads();
        if (tid == 0) {
            u64 bb = wpart[0];
            #pragma unroll
            for (int w = 1; w < 4; w++) { u64 o = wpart[w]; bb = o < bb ? o : bb; }
            int i = (int)((bb >> 8) & 0x3FFu);
            int j = (int)(bb & 0xFFu);
            s_src[t] = i;
            s_tgt[t] = j;
            s_i = i;
            colkey[j] = ~0ull;
            rowdead[i >> 5] |= (1u << (i & 31));
            s_cnt = 0;
        }
        __syncthreads();
        if (t == NT - 1) break;

        // ---- columns whose cached min-row just died ----
        const int i = s_i;
        if (tid < NT) {
            u64 kk = colkey[tid];
            if (kk != ~0ull && (int)((kk >> 8) & 0x3FFu) == i) {
                int p = atomicAdd(&s_cnt, 1);
                list_[p] = tid;
            }
        }
        __syncthreads();

        const int n = s_cnt;
        if (n) {
            for (int idx = wid; idx < n; idx += 8) {
                const int j2 = list_[idx];
                u64 best = ~0ull;
                for (int q = lane; q < NQ; q += 32) {
                    if ((rowdead[q >> 5] >> (q & 31)) & 1u) continue;
                    float v = Cb[q * NT + j2];
                    u64 kk = ((u64)f2ord(v) << 18) | ((u32)q << 8) | (u32)j2;
                    best = kk < best ? kk : best;
                }
                #pragma unroll
                for (int o = 16; o; o >>= 1) {
                    u64 ok = __shfl_down_sync(0xffffffffu, best, o);
                    best = ok < best ? ok : best;
                }
                if (lane == 0) colkey[j2] = best;
            }
            __syncthreads();
        }
    }

    __syncthreads();
    if (tid < NT) {
        out[b * NT + tid]           = (float)s_src[tid];
        out[NB * NT + b * NT + tid] = (float)s_tgt[tid];
    }
}

// ---------------------------------------------------------------------------
extern "C" void kernel_launch(void* const* d_in, const int* in_sizes, int n_in,
                              void* d_out, int out_size) {
    const float* logits = (const float*)d_in[0];   // [64,900,91]
    const float* pboxes = (const float*)d_in[1];   // [64,900,4]
    const int*   labels = (const int*)d_in[2];     // [64,128]
    const float* tboxes = (const float*)d_in[3];   // [64,128,4]
    float* out = (float*)d_out;

    float* Cout = out + 2 * NB * NT;   // C follows the two index blocks

    dim3 grid1((NQ + 15) / 16, NB);    // 57 x 64, 2 rows/warp
    cost_kernel<<<grid1, 256>>>(logits, pboxes, labels, tboxes, Cout);

    greedy_kernel<<<NB, 256>>>(Cout, out);
}

// round 4
// speedup vs baseline: 3.8823x; 1.3444x over previous
#include <cuda_runtime.h>
#include <cuda_bf16.h>
#include <stdint.h>
#include <math.h>

#define NB   64
#define NQ   900
#define NT   128
#define NCLS 91
#define CTS  912   // padded column stride (multiple of 16, > NQ+12)

typedef unsigned long long u64;
typedef unsigned int       u32;

// Transposed cost copy: g_Ct[b][col][q], column-contiguous for rescans.
__device__ float g_Ct[(size_t)NB * NT * CTS];

// monotonic float -> uint mapping (ascending)
__device__ __forceinline__ u32 f2ord(float f) {
    u32 u = __float_as_uint(f);
    return (u & 0x80000000u) ? ~u : (u | 0x80000000u);
}

__device__ __forceinline__ u64 umin64(u64 a, u64 b) { return a < b ? a : b; }

// ---------------------------------------------------------------------------
// Kernel 1: cost matrix (row-major to out) + transposed copy (to g_Ct).
// 256 threads = 8 warps; each warp computes 2 rows; block covers 16 rows.
// ---------------------------------------------------------------------------
__global__ void __launch_bounds__(256) cost_kernel(
    const float* __restrict__ logits,   // [B,Q,91]
    const float* __restrict__ pboxes,   // [B,Q,4]
    const int*   __restrict__ labels,   // [B,T]
    const float* __restrict__ tboxes,   // [B,T,4]
    float* __restrict__ Cout)           // [B,Q,T]
{
    const int b    = blockIdx.y;
    const int tid  = threadIdx.x;
    const int lane = tid & 31;
    const int wid  = tid >> 5;
    const int q0   = blockIdx.x * 16;

    __shared__ float4 s_tb[NT];
    __shared__ float4 s_tx[NT];
    __shared__ float  s_ta[NT];
    __shared__ int    s_lab[NT];
    __shared__ float  s_exp[8][92];
    __shared__ float  s_t[16][132];   // [qi][col] staging tile

    if (tid < NT) {
        const float* tb = tboxes + ((size_t)b * NT + tid) * 4;
        float cx = tb[0], cy = tb[1], w = tb[2], h = tb[3];
        s_tb[tid] = make_float4(cx, cy, w, h);
        float x0 = cx - 0.5f * w, y0 = cy - 0.5f * h;
        float x1 = cx + 0.5f * w, y1 = cy + 0.5f * h;
        s_tx[tid] = make_float4(x0, y0, x1, y1);
        s_ta[tid] = (x1 - x0) * (y1 - y0);
        s_lab[tid] = labels[b * NT + tid];
    }
    __syncthreads();

    #pragma unroll
    for (int rr = 0; rr < 2; rr++) {
        const int qi = rr * 8 + wid;
        const int q  = q0 + qi;
        if (q >= NQ) continue;

        // warp-level softmax over 91 logits
        const float* lr = logits + ((size_t)b * NQ + q) * NCLS;
        float l0 = lr[lane];
        float l1 = lr[lane + 32];
        float l2 = (lane + 64 < NCLS) ? lr[lane + 64] : -INFINITY;
        float m = fmaxf(fmaxf(l0, l1), l2);
        #pragma unroll
        for (int o = 16; o; o >>= 1) m = fmaxf(m, __shfl_xor_sync(0xffffffffu, m, o));
        float e0 = expf(l0 - m), e1 = expf(l1 - m);
        float e2 = (lane + 64 < NCLS) ? expf(l2 - m) : 0.0f;
        float ssum = e0 + e1 + e2;
        #pragma unroll
        for (int o = 16; o; o >>= 1) ssum += __shfl_xor_sync(0xffffffffu, ssum, o);
        s_exp[wid][lane] = e0;
        s_exp[wid][lane + 32] = e1;
        if (lane + 64 < NCLS) s_exp[wid][lane + 64] = e2;
        __syncwarp();
        float inv = 1.0f / ssum;

        const float* pbp = pboxes + ((size_t)b * NQ + q) * 4;
        float pcx = pbp[0], pcy = pbp[1], pw = pbp[2], ph = pbp[3];
        float px0 = pcx - 0.5f * pw, py0 = pcy - 0.5f * ph;
        float px1 = pcx + 0.5f * pw, py1 = pcy + 0.5f * ph;
        float pa  = (px1 - px0) * (py1 - py0);

        float cst[4];
        #pragma unroll
        for (int r = 0; r < 4; r++) {
            int t = (lane << 2) | r;
            float4 tb = s_tb[t];
            float4 tx = s_tx[t];
            float pl  = s_exp[wid][s_lab[t]] * inv;
            float l1c = fabsf(pcx - tb.x) + fabsf(pcy - tb.y)
                      + fabsf(pw - tb.z) + fabsf(ph - tb.w);
            float ix0 = fmaxf(px0, tx.x), iy0 = fmaxf(py0, tx.y);
            float ix1 = fminf(px1, tx.z), iy1 = fminf(py1, tx.w);
            float inter = fmaxf(ix1 - ix0, 0.0f) * fmaxf(iy1 - iy0, 0.0f);
            float uni   = pa + s_ta[t] - inter;
            float iou   = inter / uni;
            float cx0 = fminf(px0, tx.x), cy0 = fminf(py0, tx.y);
            float cx1 = fmaxf(px1, tx.z), cy1 = fmaxf(py1, tx.w);
            float ac  = fmaxf(cx1 - cx0, 0.0f) * fmaxf(cy1 - cy0, 0.0f);
            float giou = iou - (ac - uni) / ac;
            cst[r] = -pl + 5.0f * l1c - 2.0f * giou;
        }

        // row-major output (coalesced float4)
        float* crow = Cout + ((size_t)b * NQ + q) * NT;
        *(float4*)(crow + (lane << 2)) = make_float4(cst[0], cst[1], cst[2], cst[3]);

        // stage for transpose
        *(float4*)(&s_t[qi][lane << 2]) = make_float4(cst[0], cst[1], cst[2], cst[3]);
    }
    __syncthreads();

    // transposed write: thread -> (col = tid>>1, half = tid&1), 8 floats = 32B
    {
        const int colg = tid >> 1;
        const int half = tid & 1;
        float v[8];
        #pragma unroll
        for (int k = 0; k < 8; k++) v[k] = s_t[half * 8 + k][colg];
        float* dst = g_Ct + ((size_t)b * NT + colg) * CTS + q0 + half * 8;
        *(float4*)(dst)     = make_float4(v[0], v[1], v[2], v[3]);
        *(float4*)(dst + 4) = make_float4(v[4], v[5], v[6], v[7]);
    }
}

// ---------------------------------------------------------------------------
// Kernel 2: greedy matching, per-column cached minima, warp-0 argmin,
// poisoned-row transposed rescans.  One block (256 thr) per batch.
// key = (f2ord(cost)<<18) | (row<<8) | col  == flattened argmin order.
// ---------------------------------------------------------------------------
__global__ void __launch_bounds__(256) greedy_kernel(
    const float* __restrict__ Cmat,    // [B,Q,T] row-major (for init)
    float* __restrict__ out)
{
    const int b    = blockIdx.x;
    const int tid  = threadIdx.x;
    const int lane = tid & 31;
    const int wid  = tid >> 5;
    const float* __restrict__ Cb = Cmat + (size_t)b * NQ * NT;
    float* __restrict__ Ct = g_Ct + (size_t)b * NT * CTS;

    __shared__ u64 colkey[NT];
    __shared__ int s_i;
    __shared__ int s_src[NT], s_tgt[NT];

    if (tid < NT) colkey[tid] = ~0ull;
    __syncthreads();

    // init: 2 threads per column, coalesced row-major reads
    {
        const int j = tid & 127;
        u64 best = ~0ull;
        #pragma unroll 4
        for (int q = (tid >> 7); q < NQ; q += 2) {
            u64 k = ((u64)f2ord(Cb[q * NT + j]) << 18) | ((u32)q << 8) | (u32)j;
            best = umin64(best, k);
        }
        atomicMin(&colkey[j], best);
    }
    __syncthreads();

    for (int t = 0; t < NT; t++) {
        // ---- Phase A: warp 0 argmin over 128 keys ----
        if (wid == 0) {
            u64 k = umin64(umin64(colkey[lane], colkey[lane + 32]),
                           umin64(colkey[lane + 64], colkey[lane + 96]));
            #pragma unroll
            for (int o = 16; o; o >>= 1)
                k = umin64(k, __shfl_down_sync(0xffffffffu, k, o));
            if (lane == 0) {
                int i = (int)((k >> 8) & 0x3FFu);
                int j = (int)(k & 0xFFu);
                s_src[t] = i;
                s_tgt[t] = j;
                s_i = i;
                colkey[j] = ~0ull;
            }
        }
        __syncthreads();
        if (t == NT - 1) break;

        const int i = s_i;
        const int colp = (wid << 4) + lane;   // valid for lane < 16

        // ---- poison dead row i in all 128 transposed columns ----
        if (lane < 16) Ct[(size_t)colp * CTS + i] = __int_as_float(0x7F800000);

        // ---- detect + rescan dirty columns (each warp owns 16 cols) ----
        bool dirty = false;
        if (lane < 16) {
            u64 kk = colkey[colp];
            dirty = ((int)((kk >> 8) & 0x3FFu) == i);
        }
        u32 mask = __ballot_sync(0xffffffffu, dirty);
        while (mask) {
            const int c = (wid << 4) + (__ffs(mask) - 1);
            mask &= mask - 1;
            const float* col = Ct + (size_t)c * CTS;
            u64 best = ~0ull;
            #pragma unroll 4
            for (int q = lane; q < NQ; q += 32) {
                u64 kk = ((u64)f2ord(col[q]) << 18) | ((u32)q << 8) | (u32)c;
                if (q == i) kk = ~0ull;     // current-step death (race-safe skip)
                best = umin64(best, kk);
            }
            #pragma unroll
            for (int o = 16; o; o >>= 1)
                best = umin64(best, __shfl_down_sync(0xffffffffu, best, o));
            if (lane == 0) colkey[c] = best;
        }
        __syncthreads();
    }

    __syncthreads();
    if (tid < NT) {
        out[b * NT + tid]           = (float)s_src[tid];
        out[NB * NT + b * NT + tid] = (float)s_tgt[tid];
    }
}

// ---------------------------------------------------------------------------
extern "C" void kernel_launch(void* const* d_in, const int* in_sizes, int n_in,
                              void* d_out, int out_size) {
    const float* logits = (const float*)d_in[0];   // [64,900,91]
    const float* pboxes = (const float*)d_in[1];   // [64,900,4]
    const int*   labels = (const int*)d_in[2];     // [64,128]
    const float* tboxes = (const float*)d_in[3];   // [64,128,4]
    float* out = (float*)d_out;

    float* Cout = out + 2 * NB * NT;   // C follows the two index blocks

    dim3 grid1((NQ + 15) / 16, NB);    // 57 x 64
    cost_kernel<<<grid1, 256>>>(logits, pboxes, labels, tboxes, Cout);

    greedy_kernel<<<NB, 256>>>(Cout, out);
}